// round 4
// baseline (speedup 1.0000x reference)
#include <cuda_runtime.h>
#include <math.h>

#define B_SZ   16384
#define D_IN   512
#define HID    512
#define K_DIM  1024
#define N_DIM  2048
#define EPS    1e-5f

// scratch for z = cat(x,h) @ W + b   (16384 x 2048 fp32 = 128 MiB)
__device__ float g_z[(size_t)B_SZ * N_DIM];

// ---------------------------------------------------------------------------
// Kernel 1: tiled SGEMM  z[m][n] = sum_k A[m][k] * W[k][n] + bias[n]
//   A = cat(x, h) along k (k<512 -> x, else h). BK=16 divides 512 so each
//   k-tile reads from exactly one source. Double-buffered smem pipeline.
// ---------------------------------------------------------------------------
#define BM 128
#define BN 128
#define BK 16
#define TM 8
#define TN 8

__device__ __forceinline__ float4 ldA4(const float* __restrict__ x,
                                       const float* __restrict__ h,
                                       int m, int k)
{
    return (k < D_IN)
        ? *reinterpret_cast<const float4*>(x + (size_t)m * D_IN + k)
        : *reinterpret_cast<const float4*>(h + (size_t)m * HID + (k - D_IN));
}

__global__ __launch_bounds__(256) void gemm_kernel(
    const float* __restrict__ x, const float* __restrict__ h,
    const float* __restrict__ W, const float* __restrict__ bias)
{
    __shared__ float As[2][BK][BM];
    __shared__ float Bs[2][BK][BN];

    const int tid = threadIdx.x;
    const int tx = tid & 15;          // 0..15 -> n direction
    const int ty = tid >> 4;          // 0..15 -> m direction
    const int m0 = blockIdx.y * BM;
    const int n0 = blockIdx.x * BN;

    // A-tile load coords (2 float4 per thread)
    const int aR0 = tid >> 2;                 // 0..63
    const int aC  = (tid & 3) * 4;            // 0,4,8,12
    const int aR1 = aR0 + 64;                 // 64..127
    // B-tile load coords (2 float4 per thread)
    const int bR0 = tid >> 5;                 // 0..7
    const int bC  = (tid & 31) * 4;           // 0..124
    const int bR1 = bR0 + 8;                  // 8..15

    float acc[TM][TN];
#pragma unroll
    for (int i = 0; i < TM; i++)
#pragma unroll
        for (int j = 0; j < TN; j++) acc[i][j] = 0.0f;

    // prologue: load tile 0 into buffer 0
    {
        float4 a0 = ldA4(x, h, m0 + aR0, aC);
        float4 a1 = ldA4(x, h, m0 + aR1, aC);
        float4 b0 = *reinterpret_cast<const float4*>(W + (size_t)bR0 * N_DIM + n0 + bC);
        float4 b1 = *reinterpret_cast<const float4*>(W + (size_t)bR1 * N_DIM + n0 + bC);
        As[0][aC + 0][aR0] = a0.x; As[0][aC + 1][aR0] = a0.y;
        As[0][aC + 2][aR0] = a0.z; As[0][aC + 3][aR0] = a0.w;
        As[0][aC + 0][aR1] = a1.x; As[0][aC + 1][aR1] = a1.y;
        As[0][aC + 2][aR1] = a1.z; As[0][aC + 3][aR1] = a1.w;
        *reinterpret_cast<float4*>(&Bs[0][bR0][bC]) = b0;
        *reinterpret_cast<float4*>(&Bs[0][bR1][bC]) = b1;
    }
    __syncthreads();

    int cur = 0;
    for (int k0 = 0; k0 < K_DIM; k0 += BK) {
        const bool has_next = (k0 + BK) < K_DIM;
        float4 a0, a1, b0, b1;
        if (has_next) {
            const int kn = k0 + BK;
            a0 = ldA4(x, h, m0 + aR0, kn + aC);
            a1 = ldA4(x, h, m0 + aR1, kn + aC);
            b0 = *reinterpret_cast<const float4*>(W + (size_t)(kn + bR0) * N_DIM + n0 + bC);
            b1 = *reinterpret_cast<const float4*>(W + (size_t)(kn + bR1) * N_DIM + n0 + bC);
        }

#pragma unroll
        for (int k = 0; k < BK; k++) {
            float ra[TM], rb[TN];
#pragma unroll
            for (int i = 0; i < TM; i++) ra[i] = As[cur][k][ty * TM + i];
#pragma unroll
            for (int j = 0; j < TN; j++) rb[j] = Bs[cur][k][tx * TN + j];
#pragma unroll
            for (int i = 0; i < TM; i++)
#pragma unroll
                for (int j = 0; j < TN; j++)
                    acc[i][j] = fmaf(ra[i], rb[j], acc[i][j]);
        }

        if (has_next) {
            const int nxt = cur ^ 1;
            As[nxt][aC + 0][aR0] = a0.x; As[nxt][aC + 1][aR0] = a0.y;
            As[nxt][aC + 2][aR0] = a0.z; As[nxt][aC + 3][aR0] = a0.w;
            As[nxt][aC + 0][aR1] = a1.x; As[nxt][aC + 1][aR1] = a1.y;
            As[nxt][aC + 2][aR1] = a1.z; As[nxt][aC + 3][aR1] = a1.w;
            *reinterpret_cast<float4*>(&Bs[nxt][bR0][bC]) = b0;
            *reinterpret_cast<float4*>(&Bs[nxt][bR1][bC]) = b1;
            __syncthreads();
            cur = nxt;
        }
    }

#pragma unroll
    for (int i = 0; i < TM; i++) {
        int m = m0 + ty * TM + i;
#pragma unroll
        for (int j = 0; j < TN; j++) {
            int n = n0 + tx * TN + j;
            g_z[(size_t)m * N_DIM + n] = acc[i][j] + bias[n];
        }
    }
}

// ---------------------------------------------------------------------------
// Kernel 2: fused GroupNorm(4) + FiLM + LSTM gates + GroupNorm(1) + output.
// One block (512 threads) per batch row. Thread t owns z[t], z[t+512],
// z[t+1024], z[t+1536] -> one element of each gate AND each of the 4 groups.
// ---------------------------------------------------------------------------
__device__ __forceinline__ float sigmoidf_(float v) {
    return 1.0f / (1.0f + expf(-v));
}

__global__ __launch_bounds__(512) void fused_kernel(
    const float* __restrict__ c, const float* __restrict__ u,
    const float* __restrict__ gamma, const float* __restrict__ beta,
    float* __restrict__ out)
{
    const int row  = blockIdx.x;
    const int t    = threadIdx.x;          // 0..511
    const int warp = t >> 5;
    const int lane = t & 31;

    const float* zr = g_z + (size_t)row * N_DIM;
    float z[4];
    z[0] = zr[t];           // i (group 0)
    z[1] = zr[t + 512];     // f (group 1)
    z[2] = zr[t + 1024];    // o (group 2)
    z[3] = zr[t + 1536];    // g (group 3)

    __shared__ float sred[16][8];
    __shared__ float sfin[8];

    // ----- phase 1: per-group sum & sumsq (8 simultaneous block reductions)
    float p[8];
#pragma unroll
    for (int q = 0; q < 4; q++) { p[q] = z[q]; p[4 + q] = z[q] * z[q]; }
#pragma unroll
    for (int off = 16; off > 0; off >>= 1)
#pragma unroll
        for (int q = 0; q < 8; q++)
            p[q] += __shfl_down_sync(0xFFFFFFFFu, p[q], off);
    if (lane == 0)
#pragma unroll
        for (int q = 0; q < 8; q++) sred[warp][q] = p[q];
    __syncthreads();
    if (t < 8) {
        float s = 0.0f;
#pragma unroll
        for (int w = 0; w < 16; w++) s += sred[w][t];
        sfin[t] = s;
    }
    __syncthreads();

    float mean[4], rstd[4];
#pragma unroll
    for (int g = 0; g < 4; g++) {
        mean[g] = sfin[g] * (1.0f / 512.0f);
        float var = sfin[4 + g] * (1.0f / 512.0f) - mean[g] * mean[g];
        rstd[g] = rsqrtf(var + EPS);
    }

    // ----- FiLM: z = z_norm * (1 + a) + b,   a = u[:, :2048], b = u[:, 2048:]
    const float* ur = u + (size_t)row * (2 * N_DIM);
    float zn[4];
#pragma unroll
    for (int g = 0; g < 4; g++) {
        int idx = g * 512 + t;
        float a  = ur[idx];
        float bb = ur[N_DIM + idx];
        zn[g] = (z[g] - mean[g]) * rstd[g] * (1.0f + a) + bb;
    }

    // ----- LSTM cell update
    float cv    = c[(size_t)row * HID + t];
    float c_new = sigmoidf_(zn[1]) * cv + sigmoidf_(zn[0]) * tanhf(zn[3]);

    // ----- phase 2: GroupNorm(1) over c_new (512 values)
    float s = c_new, ss = c_new * c_new;
#pragma unroll
    for (int off = 16; off > 0; off >>= 1) {
        s  += __shfl_down_sync(0xFFFFFFFFu, s, off);
        ss += __shfl_down_sync(0xFFFFFFFFu, ss, off);
    }
    if (lane == 0) { sred[warp][0] = s; sred[warp][1] = ss; }
    __syncthreads();
    if (t < 2) {
        float acc = 0.0f;
#pragma unroll
        for (int w = 0; w < 16; w++) acc += sred[w][t];
        sfin[t] = acc;
    }
    __syncthreads();

    float m2 = sfin[0] * (1.0f / 512.0f);
    float v2 = sfin[1] * (1.0f / 512.0f) - m2 * m2;
    float cn = (c_new - m2) * rsqrtf(v2 + EPS) * gamma[t] + beta[t];

    float h_new = sigmoidf_(zn[2]) * tanhf(cn);

    out[(size_t)row * HID + t] = h_new;                              // h_new
    out[(size_t)B_SZ * HID + (size_t)row * HID + t] = c_new;         // c_new
}

// ---------------------------------------------------------------------------
extern "C" void kernel_launch(void* const* d_in, const int* in_sizes, int n_in,
                              void* d_out, int out_size)
{
    const float* x     = (const float*)d_in[0];
    const float* h     = (const float*)d_in[1];
    const float* c     = (const float*)d_in[2];
    const float* u     = (const float*)d_in[3];
    const float* W     = (const float*)d_in[4];
    const float* b_lin = (const float*)d_in[5];
    const float* gamma = (const float*)d_in[6];
    const float* beta  = (const float*)d_in[7];
    float* out = (float*)d_out;

    dim3 grid_gemm(N_DIM / BN, B_SZ / BM);   // (16, 128)
    gemm_kernel<<<grid_gemm, 256>>>(x, h, W, b_lin);
    fused_kernel<<<B_SZ, 512>>>(c, u, gamma, beta, out);
}

// round 7
// speedup vs baseline: 2.4880x; 2.4880x over previous
#include <cuda_runtime.h>
#include <cuda_bf16.h>
#include <math.h>
#include <stdint.h>

#define B_SZ   16384
#define D_IN   512
#define HID    512
#define K_DIM  1024
#define N_DIM  2048
#define EPS    1e-5f

// ---------------- device scratch ----------------
__device__ float          g_z[(size_t)B_SZ * N_DIM];          // 128 MB
__device__ __nv_bfloat16  g_Ahi[(size_t)B_SZ * K_DIM];        // 32 MB
__device__ __nv_bfloat16  g_Alo[(size_t)B_SZ * K_DIM];        // 32 MB
__device__ __nv_bfloat16  g_Bhi[(size_t)N_DIM * K_DIM];       // 4 MB  [N,K]
__device__ __nv_bfloat16  g_Blo[(size_t)N_DIM * K_DIM];       // 4 MB

// ---------------- helpers (all base-sm_103 features, no 'a' suffix) --------
__device__ __forceinline__ uint32_t smem_u32(const void* p) {
    uint32_t a;
    asm("{ .reg .u64 t; cvta.to.shared.u64 t, %1; cvt.u32.u64 %0, t; }" : "=r"(a) : "l"(p));
    return a;
}
__device__ __forceinline__ void cp_async16(uint32_t dst, const void* src) {
    asm volatile("cp.async.cg.shared.global [%0], [%1], 16;" :: "r"(dst), "l"(src) : "memory");
}
#define CP_COMMIT()  asm volatile("cp.async.commit_group;" ::: "memory")
#define CP_WAIT(n)   asm volatile("cp.async.wait_group %0;" :: "n"(n) : "memory")

__device__ __forceinline__ void ldsm_x4(uint32_t (&r)[4], uint32_t addr) {
    asm volatile("ldmatrix.sync.aligned.m8n8.x4.shared.b16 {%0,%1,%2,%3}, [%4];"
        : "=r"(r[0]), "=r"(r[1]), "=r"(r[2]), "=r"(r[3]) : "r"(addr));
}
__device__ __forceinline__ void mma_bf16(float (&d)[4], const uint32_t (&a)[4],
                                         const uint32_t* b) {
    asm volatile(
        "mma.sync.aligned.m16n8k16.row.col.f32.bf16.bf16.f32 "
        "{%0,%1,%2,%3}, {%4,%5,%6,%7}, {%8,%9}, {%0,%1,%2,%3};"
        : "+f"(d[0]), "+f"(d[1]), "+f"(d[2]), "+f"(d[3])
        : "r"(a[0]), "r"(a[1]), "r"(a[2]), "r"(a[3]), "r"(b[0]), "r"(b[1]));
}

// ---------------------------------------------------------------------------
// convA: cat(x,h) fp32 -> bf16 hi/lo, [B_SZ, K_DIM] K-major
// ---------------------------------------------------------------------------
__global__ __launch_bounds__(256) void convA_kernel(
    const float* __restrict__ x, const float* __restrict__ h)
{
    int gid = blockIdx.x * 256 + threadIdx.x;       // one float4 per thread
    int m   = gid >> 8;                             // 256 float4 per row
    int c4  = (gid & 255) * 4;
    float4 v = (c4 < D_IN)
        ? *reinterpret_cast<const float4*>(x + (size_t)m * D_IN + c4)
        : *reinterpret_cast<const float4*>(h + (size_t)m * HID + (c4 - D_IN));
    float f[4] = {v.x, v.y, v.z, v.w};
    __nv_bfloat16 hi[4], lo[4];
#pragma unroll
    for (int i = 0; i < 4; i++) {
        hi[i] = __float2bfloat16_rn(f[i]);
        lo[i] = __float2bfloat16_rn(f[i] - __bfloat162float(hi[i]));
    }
    size_t o = (size_t)m * K_DIM + c4;
    *reinterpret_cast<uint2*>(&g_Ahi[o]) = *reinterpret_cast<uint2*>(hi);
    *reinterpret_cast<uint2*>(&g_Alo[o]) = *reinterpret_cast<uint2*>(lo);
}

// ---------------------------------------------------------------------------
// convW: W[K,N] fp32 -> Wt hi/lo [N,K] bf16 (transposed, K-major)
// ---------------------------------------------------------------------------
__global__ __launch_bounds__(1024) void convW_kernel(const float* __restrict__ W)
{
    __shared__ float tile[32][33];
    int tx = threadIdx.x, ty = threadIdx.y;
    int n0 = blockIdx.x * 32, k0 = blockIdx.y * 32;
    tile[ty][tx] = W[(size_t)(k0 + ty) * N_DIM + n0 + tx];
    __syncthreads();
    float v = tile[tx][ty];                  // = W[k0+tx][n0+ty]
    __nv_bfloat16 hi = __float2bfloat16_rn(v);
    __nv_bfloat16 lo = __float2bfloat16_rn(v - __bfloat162float(hi));
    size_t o = (size_t)(n0 + ty) * K_DIM + k0 + tx;
    g_Bhi[o] = hi;
    g_Blo[o] = lo;
}

// ---------------------------------------------------------------------------
// HMMA GEMM: z[128x128 tile] = Ahi@Bhi^T + Ahi@Blo^T + Alo@Bhi^T + bias
// 8 warps (2x4), warp tile 64x32, K-chunk 32, double-buffered cp.async.
// smem stage: Ahi | Alo | Bhi | Blo, each 128 rows x 32 bf16, row stride 80B.
// ---------------------------------------------------------------------------
#define KC        32
#define NCHUNK    (K_DIM / KC)            // 32
#define ROW_B     80                      // padded row stride in bytes
#define OP_SZ     (128 * ROW_B)           // 10240
#define STG_SZ    (4 * OP_SZ)             // 40960
#define CTRL_SZ   1024
#define SMEM_TOTAL (CTRL_SZ + 2 * STG_SZ) // 82944
#define OFF_ALO   OP_SZ
#define OFF_BHI   (2 * OP_SZ)
#define OFF_BLO   (3 * OP_SZ)

__global__ __launch_bounds__(256) void gemm_tc_kernel(const float* __restrict__ bias)
{
    extern __shared__ char smem[];
    const uint32_t sb = smem_u32(smem);
    const int tid  = threadIdx.x;
    const int wid  = tid >> 5;
    const int lane = tid & 31;
    const int wm   = wid >> 2;            // 0..1  (64-row slab)
    const int wn   = wid & 3;             // 0..3  (32-col slab)
    const int n0 = blockIdx.x * 128;
    const int m0 = blockIdx.y * 128;

    float* sbias = reinterpret_cast<float*>(smem);
    if (tid < 128) sbias[tid] = bias[n0 + tid];

    // ---- stage loader: 2048 x 16B cp.async, 8 per thread
    auto load_stage = [&](int s, int kc) {
        const uint32_t stg = sb + CTRL_SZ + s * STG_SZ;
        const int k0 = kc * KC;
#pragma unroll
        for (int it = 0; it < 8; it++) {
            int e = it * 256 + tid;                  // 0..2047
            int o = e >> 9;                          // operand 0..3
            int idx = e & 511;
            int r = idx >> 2;                        // row 0..127
            int j = idx & 3;                         // 16B chunk in row
            uint32_t dst = stg + o * OP_SZ + r * ROW_B + j * 16;
            const __nv_bfloat16* src;
            if (o == 0)      src = g_Ahi + (size_t)(m0 + r) * K_DIM + k0 + j * 8;
            else if (o == 1) src = g_Alo + (size_t)(m0 + r) * K_DIM + k0 + j * 8;
            else if (o == 2) src = g_Bhi + (size_t)(n0 + r) * K_DIM + k0 + j * 8;
            else             src = g_Blo + (size_t)(n0 + r) * K_DIM + k0 + j * 8;
            cp_async16(dst, src);
        }
        CP_COMMIT();
    };

    float acc[4][4][4];
#pragma unroll
    for (int mt = 0; mt < 4; mt++)
#pragma unroll
        for (int nt = 0; nt < 4; nt++)
#pragma unroll
            for (int e = 0; e < 4; e++) acc[mt][nt][e] = 0.0f;

    // ldmatrix lane-address components
    const int a_row_in = lane & 15;            // row within 16-row tile
    const int a_kh     = lane >> 4;            // k-half (0/1 -> +0/+16B)
    const int b_oct    = lane >> 4;            // n-octet
    const int b_kh     = (lane >> 3) & 1;      // k-half
    const int b_rin    = lane & 7;

    load_stage(0, 0);

    for (int c = 0; c < NCHUNK; c++) {
        const int cs = c & 1;
        if (c + 1 < NCHUNK) { load_stage(cs ^ 1, c + 1); CP_WAIT(1); }
        else                { CP_WAIT(0); }
        __syncthreads();

        const uint32_t stg = sb + CTRL_SZ + cs * STG_SZ;
        const uint32_t aBase = stg + (wm * 64 + a_row_in) * ROW_B + a_kh * 16;
        const uint32_t bBase = stg + OFF_BHI
                             + (wn * 32 + b_oct * 8 + b_rin) * ROW_B + b_kh * 16;

#pragma unroll
        for (int ks = 0; ks < 2; ks++) {          // two k16 slices per chunk
            uint32_t ahi[4][4], alo[4][4], bhi[2][4], blo[2][4];
#pragma unroll
            for (int mt = 0; mt < 4; mt++) {
                uint32_t ad = aBase + mt * (16 * ROW_B) + ks * 32;
                ldsm_x4(ahi[mt], ad);
                ldsm_x4(alo[mt], ad + OFF_ALO);
            }
#pragma unroll
            for (int bt = 0; bt < 2; bt++) {
                uint32_t bd = bBase + bt * (16 * ROW_B) + ks * 32;
                ldsm_x4(bhi[bt], bd);
                ldsm_x4(blo[bt], bd + OP_SZ);     // Blo is right after Bhi
            }
#pragma unroll
            for (int mt = 0; mt < 4; mt++)
#pragma unroll
                for (int nt = 0; nt < 4; nt++) {
                    const int bt = nt >> 1, oj = (nt & 1) * 2;
                    mma_bf16(acc[mt][nt], ahi[mt], &bhi[bt][oj]);
                    mma_bf16(acc[mt][nt], ahi[mt], &blo[bt][oj]);
                    mma_bf16(acc[mt][nt], alo[mt], &bhi[bt][oj]);
                }
        }
        __syncthreads();
    }

    // ---- epilogue: acc -> g_z (+bias)
    const int g   = lane >> 2;
    const int tig = lane & 3;
#pragma unroll
    for (int mt = 0; mt < 4; mt++) {
        int row0 = m0 + wm * 64 + mt * 16 + g;
#pragma unroll
        for (int nt = 0; nt < 4; nt++) {
            int ncol = wn * 32 + nt * 8 + tig * 2;
            float b0 = sbias[ncol], b1 = sbias[ncol + 1];
            float2 v0 = make_float2(acc[mt][nt][0] + b0, acc[mt][nt][1] + b1);
            float2 v1 = make_float2(acc[mt][nt][2] + b0, acc[mt][nt][3] + b1);
            *reinterpret_cast<float2*>(g_z + (size_t)row0 * N_DIM + n0 + ncol) = v0;
            *reinterpret_cast<float2*>(g_z + (size_t)(row0 + 8) * N_DIM + n0 + ncol) = v1;
        }
    }
}

// ---------------------------------------------------------------------------
// fused GroupNorm(4) + FiLM + LSTM + GroupNorm(1) (validated R4; 110us)
// ---------------------------------------------------------------------------
__device__ __forceinline__ float sigmoidf_(float v) {
    return 1.0f / (1.0f + expf(-v));
}

__global__ __launch_bounds__(512) void fused_kernel(
    const float* __restrict__ c, const float* __restrict__ u,
    const float* __restrict__ gamma, const float* __restrict__ beta,
    float* __restrict__ out)
{
    const int row  = blockIdx.x;
    const int t    = threadIdx.x;
    const int warp = t >> 5;
    const int lane = t & 31;

    const float* zr = g_z + (size_t)row * N_DIM;
    float z[4];
    z[0] = zr[t];
    z[1] = zr[t + 512];
    z[2] = zr[t + 1024];
    z[3] = zr[t + 1536];

    __shared__ float sred[16][8];
    __shared__ float sfin[8];

    float p[8];
#pragma unroll
    for (int q = 0; q < 4; q++) { p[q] = z[q]; p[4 + q] = z[q] * z[q]; }
#pragma unroll
    for (int off = 16; off > 0; off >>= 1)
#pragma unroll
        for (int q = 0; q < 8; q++)
            p[q] += __shfl_down_sync(0xFFFFFFFFu, p[q], off);
    if (lane == 0)
#pragma unroll
        for (int q = 0; q < 8; q++) sred[warp][q] = p[q];
    __syncthreads();
    if (t < 8) {
        float s = 0.0f;
#pragma unroll
        for (int w = 0; w < 16; w++) s += sred[w][t];
        sfin[t] = s;
    }
    __syncthreads();

    float mean[4], rstd[4];
#pragma unroll
    for (int g = 0; g < 4; g++) {
        mean[g] = sfin[g] * (1.0f / 512.0f);
        float var = sfin[4 + g] * (1.0f / 512.0f) - mean[g] * mean[g];
        rstd[g] = rsqrtf(var + EPS);
    }

    const float* ur = u + (size_t)row * (2 * N_DIM);
    float zn[4];
#pragma unroll
    for (int g = 0; g < 4; g++) {
        int idx = g * 512 + t;
        float a  = ur[idx];
        float bb = ur[N_DIM + idx];
        zn[g] = (z[g] - mean[g]) * rstd[g] * (1.0f + a) + bb;
    }

    float cv    = c[(size_t)row * HID + t];
    float c_new = sigmoidf_(zn[1]) * cv + sigmoidf_(zn[0]) * tanhf(zn[3]);

    float s = c_new, ss = c_new * c_new;
#pragma unroll
    for (int off = 16; off > 0; off >>= 1) {
        s  += __shfl_down_sync(0xFFFFFFFFu, s, off);
        ss += __shfl_down_sync(0xFFFFFFFFu, ss, off);
    }
    if (lane == 0) { sred[warp][0] = s; sred[warp][1] = ss; }
    __syncthreads();
    if (t < 2) {
        float acc = 0.0f;
#pragma unroll
        for (int w = 0; w < 16; w++) acc += sred[w][t];
        sfin[t] = acc;
    }
    __syncthreads();

    float m2 = sfin[0] * (1.0f / 512.0f);
    float v2 = sfin[1] * (1.0f / 512.0f) - m2 * m2;
    float cn = (c_new - m2) * rsqrtf(v2 + EPS) * gamma[t] + beta[t];

    float h_new = sigmoidf_(zn[2]) * tanhf(cn);

    out[(size_t)row * HID + t] = h_new;
    out[(size_t)B_SZ * HID + (size_t)row * HID + t] = c_new;
}

// ---------------------------------------------------------------------------
extern "C" void kernel_launch(void* const* d_in, const int* in_sizes, int n_in,
                              void* d_out, int out_size)
{
    const float* x     = (const float*)d_in[0];
    const float* h     = (const float*)d_in[1];
    const float* c     = (const float*)d_in[2];
    const float* u     = (const float*)d_in[3];
    const float* W     = (const float*)d_in[4];
    const float* b_lin = (const float*)d_in[5];
    const float* gamma = (const float*)d_in[6];
    const float* beta  = (const float*)d_in[7];
    float* out = (float*)d_out;

    cudaFuncSetAttribute(gemm_tc_kernel,
                         cudaFuncAttributeMaxDynamicSharedMemorySize, SMEM_TOTAL);

    convA_kernel<<<(B_SZ * K_DIM / 4) / 256, 256>>>(x, h);
    convW_kernel<<<dim3(N_DIM / 32, K_DIM / 32), dim3(32, 32)>>>(W);
    gemm_tc_kernel<<<dim3(N_DIM / 128, B_SZ / 128), 256, SMEM_TOTAL>>>(b_lin);
    fused_kernel<<<B_SZ, 512>>>(c, u, gamma, beta, out);
}